// round 11
// baseline (speedup 1.0000x reference)
#include <cuda_runtime.h>

// ---------------------------------------------------------------------------
// SSIM fused kernel: persistent CTAs + 16B cp.async prefetch, sm_100a.
// (16,3,512,512) fp32 pairs -> mean SSIM.
// R11 = R9 resubmit (R10 was an infra failure; R9 never measured):
//   16B-aligned zfill prefetch (origin tx0-8), div-free mapping,
//   phase-3 re-indexed for the new origin (re-audited).
// ---------------------------------------------------------------------------

#define IMG_H 512
#define IMG_W 512
#define TW 128
#define TH 16
#define IH 26                 // TH + 10
#define SI_PITCH 72           // input smem pitch in float2 units (36 quads)
#define NQUAD 36              // 16B quads per input row
#define NXP 71                // colsum x-pairs per row (pairs 0..70)
#define CS_PITCH 71           // colsum pitch (float2), odd -> conflict-free
#define NTHREADS 288
#define NWARPS 9
#define NB 444                // persistent blocks = 148 SMs x 3 CTAs
#define NTILES (48 * 32 * 4)  // planes x by x bx = 6144

typedef unsigned long long ull;

// ---- compile-time Gaussian weights, double precision (match numpy) --------
constexpr double expser(double x) {
    double t = 1.0, s = 1.0;
    for (int k = 1; k < 100; k++) { t = t * x / (double)k; s += t; }
    return s;
}
constexpr double gk(int i) { double d = (double)(i - 5); return 1.0 / expser(d * d / 4.5); }
constexpr double GSUM = gk(0)+gk(1)+gk(2)+gk(3)+gk(4)+gk(5)+gk(6)+gk(7)+gk(8)+gk(9)+gk(10);
constexpr float WF(int i) { return (float)(gk(i) / GSUM); }
__device__ constexpr float W[11] = {WF(0),WF(1),WF(2),WF(3),WF(4),WF(5),
                                    WF(6),WF(7),WF(8),WF(9),WF(10)};

// ---- f32x2 packed helpers -------------------------------------------------
__device__ __forceinline__ ull fma2(ull a, ull b, ull c) {
    ull d;
    asm("fma.rn.f32x2 %0, %1, %2, %3;" : "=l"(d) : "l"(a), "l"(b), "l"(c));
    return d;
}
__device__ __forceinline__ ull mul2(ull a, ull b) {
    ull d;
    asm("mul.rn.f32x2 %0, %1, %2;" : "=l"(d) : "l"(a), "l"(b));
    return d;
}
__device__ __forceinline__ ull add2(ull a, ull b) {
    ull d;
    asm("add.rn.f32x2 %0, %1, %2;" : "=l"(d) : "l"(a), "l"(b));
    return d;
}
__device__ __forceinline__ ull bc2(float w) {
    ull u;
    asm("mov.b64 %0, {%1, %1};" : "=l"(u) : "f"(w));
    return u;
}
__device__ __forceinline__ ull pk2(float x, float y) {
    ull u;
    asm("mov.b64 %0, {%1, %2};" : "=l"(u) : "f"(x), "f"(y));
    return u;
}
__device__ __forceinline__ float lo2(ull u) {
    float x; asm("{ .reg .f32 hi; mov.b64 {%0, hi}, %1; }" : "=f"(x) : "l"(u));
    return x;
}
__device__ __forceinline__ float hi2(ull u) {
    float y; asm("{ .reg .f32 lo; mov.b64 {lo, %0}, %1; }" : "=f"(y) : "l"(u));
    return y;
}
__device__ __forceinline__ ull neg2(ull a) { return a ^ 0x8000000080000000ULL; }

__device__ double g_sum;
__device__ unsigned g_cnt;

// ---- 16B cp.async prefetch of one tile's halo'd inputs --------------------
// smem col 0 <-> gx0 = tx0 - 8 (multiple of 4 => 16B aligned globals).
// Quads are all-in or all-out of the image (gx, IMG_W both multiples of 4),
// so zfill predication reproduces the conv zero-padding exactly.
__device__ __forceinline__ void prefetch_tile(int t, int wrp, int lan,
                                              const float* __restrict__ img1,
                                              const float* __restrict__ img2,
                                              ull* sI1, ull* sI2) {
    const int bx = t & 3;
    const int by = (t >> 2) & 31;
    const int plane = t >> 7;
    const int ty0 = by * TH;
    const int gx0 = bx * TW - 8;
    const float* p1 = img1 + (size_t)plane * (IMG_H * IMG_W);
    const float* p2 = img2 + (size_t)plane * (IMG_H * IMG_W);

    for (int y = wrp; y < IH; y += NWARPS) {
        const int gy = ty0 - 5 + y;
        const bool yin = (unsigned)gy < (unsigned)IMG_H;
        const float* r1 = p1 + gy * IMG_W + gx0;
        const float* r2 = p2 + gy * IMG_W + gx0;
        unsigned d1 = (unsigned)__cvta_generic_to_shared(sI1 + y * SI_PITCH);
        unsigned d2 = (unsigned)__cvta_generic_to_shared(sI2 + y * SI_PITCH);
        {
            const int q = lan;                      // quads 0..31
            const int gx = gx0 + 4 * q;
            const int sz = (yin && (unsigned)gx < (unsigned)IMG_W) ? 16 : 0;
            asm volatile("cp.async.cg.shared.global [%0], [%1], 16, %2;"
                         :: "r"(d1 + q * 16), "l"(r1 + 4 * q), "r"(sz));
            asm volatile("cp.async.cg.shared.global [%0], [%1], 16, %2;"
                         :: "r"(d2 + q * 16), "l"(r2 + 4 * q), "r"(sz));
        }
        if (lan < NQUAD - 32) {                     // quads 32..35
            const int q = lan + 32;
            const int gx = gx0 + 4 * q;
            const int sz = (yin && (unsigned)gx < (unsigned)IMG_W) ? 16 : 0;
            asm volatile("cp.async.cg.shared.global [%0], [%1], 16, %2;"
                         :: "r"(d1 + q * 16), "l"(r1 + 4 * q), "r"(sz));
            asm volatile("cp.async.cg.shared.global [%0], [%1], 16, %2;"
                         :: "r"(d2 + q * 16), "l"(r2 + 4 * q), "r"(sz));
        }
    }
}

__global__ __launch_bounds__(NTHREADS, 3)
void ssim_main(const float* __restrict__ img1, const float* __restrict__ img2,
               float* __restrict__ out, double inv_n) {
    extern __shared__ ull smu[];
    ull* sI1 = smu;                               // IH * SI_PITCH
    ull* sI2 = smu + IH * SI_PITCH;
    ull* sCS = smu + 2 * IH * SI_PITCH;           // 5 * TH * CS_PITCH
    __shared__ double sRed[NWARPS];

    const int tid = threadIdx.x;
    const int wrp = tid >> 5;
    const int lan = tid & 31;
    const int bid = blockIdx.x;

    double td = 0.0;

    prefetch_tile(bid, wrp, lan, img1, img2, sI1, sI2);
    asm volatile("cp.async.commit_group;" ::: "memory");

    for (int t = bid; t < NTILES; t += NB) {
        asm volatile("cp.async.wait_group 0;" ::: "memory");
        __syncthreads();                          // sI ready; sCS free

        // ---- phase 2: vertical conv, all 5 quantities per task ------------
        // 284 tasks = xpair u in [0,71) x strip s in [0,4) of 4 output rows.
        if (tid < NXP * 4) {
            const int u = tid % NXP;
            const int s = tid / NXP;
            const ull* pa = sI1 + (4 * s) * SI_PITCH + u;
            const ull* pb = sI2 + (4 * s) * SI_PITCH + u;
            ull acc[5][4];
#pragma unroll
            for (int q = 0; q < 5; q++)
#pragma unroll
                for (int k = 0; k < 4; k++) acc[q][k] = 0ULL;

#pragma unroll
            for (int j = 0; j < 14; j++) {
                ull a  = pa[j * SI_PITCH];
                ull b  = pb[j * SI_PITCH];
                ull aa = mul2(a, a);
                ull bb = mul2(b, b);
                ull ab = mul2(a, b);
#pragma unroll
                for (int k = 0; k < 4; k++) {
                    if ((unsigned)(j - k) < 11u) {
                        ull wp = bc2(W[j - k]);
                        acc[0][k] = fma2(wp, a,  acc[0][k]);
                        acc[1][k] = fma2(wp, b,  acc[1][k]);
                        acc[2][k] = fma2(wp, aa, acc[2][k]);
                        acc[3][k] = fma2(wp, bb, acc[3][k]);
                        acc[4][k] = fma2(wp, ab, acc[4][k]);
                    }
                }
            }
#pragma unroll
            for (int q = 0; q < 5; q++)
#pragma unroll
                for (int k = 0; k < 4; k++)
                    sCS[(q * TH + 4 * s + k) * CS_PITCH + u] = acc[q][k];
        }
        __syncthreads();                          // sCS ready; sI free

        // ---- prefetch next tile (overlaps phase 3) ------------------------
        {
            int tn = t + NB;
            if (tn < NTILES) prefetch_tile(tn, wrp, lan, img1, img2, sI1, sI2);
            asm volatile("cp.async.commit_group;" ::: "memory");
        }

        // ---- phase 3: horizontal conv packed over x-pairs + SSIM ----------
        // Origin tx0-8, output pair n=4xb+o:
        //   shifted S[j_s]=(hi cs[j_s], lo cs[j_s+1]): even weights W[2(j_s-o-1)], j_s=o+1..o+6
        //   aligned cs[j]:                              odd weights W[2(j-o-2)+1], j=o+2..o+6
        if (tid < 256) {
            const int y  = tid & 15;
            const int xb = tid >> 4;

            ull Wp[11];
#pragma unroll
            for (int w = 0; w < 11; w++) Wp[w] = bc2(W[w]);

            ull m[5][4];
#pragma unroll
            for (int q = 0; q < 5; q++)
#pragma unroll
                for (int o = 0; o < 4; o++) m[q][o] = 0ULL;

#pragma unroll
            for (int q = 0; q < 5; q++) {
                const ull* cs = sCS + (q * TH + y) * CS_PITCH + 4 * xb;
                ull Pp = cs[1];
#pragma unroll
                for (int i = 2; i <= 10; i++) {
                    ull Pi = cs[i];
                    ull S = pk2(hi2(Pp), lo2(Pi));       // S[i-1]
#pragma unroll
                    for (int o = 0; o < 4; o++) {
                        int d = i - o - 2;
                        if (d >= 0 && d <= 5)
                            m[q][o] = fma2(Wp[2 * d], S, m[q][o]);
                        if (d >= 0 && d <= 4)
                            m[q][o] = fma2(Wp[2 * d + 1], Pi, m[q][o]);
                    }
                    Pp = Pi;
                }
            }

            const ull C1p  = bc2(1e-4f);
            const ull C2p  = bc2(9e-4f);
            const ull TWOp = bc2(2.0f);
            float local = 0.0f;
#pragma unroll
            for (int o = 0; o < 4; o++) {
                ull m1 = m[0][o], m2 = m[1][o];
                ull m1s = mul2(m1, m1);
                ull m2s = mul2(m2, m2);
                ull m12 = mul2(m1, m2);
                ull nm1 = neg2(m1);
                ull s1  = fma2(nm1, m1, m[2][o]);
                ull s2  = fma2(neg2(m2), m2, m[3][o]);
                ull s12 = fma2(nm1, m2, m[4][o]);
                ull numA = fma2(TWOp, m12, C1p);
                ull numB = fma2(TWOp, s12, C2p);
                ull denA = add2(m1s, add2(m2s, C1p));
                ull denB = add2(s1,  add2(s2,  C2p));
                ull num  = mul2(numA, numB);
                ull den  = mul2(denA, denB);
                local += __fdividef(lo2(num), lo2(den));
                local += __fdividef(hi2(num), hi2(den));
            }
            td += (double)local;
        }
    }

    // -------- final reduction (once per block) -----------------------------
    {
        unsigned mask = 0xffffffffu;
#pragma unroll
        for (int s = 16; s > 0; s >>= 1) td += __shfl_down_sync(mask, td, s);
        if (lan == 0) sRed[wrp] = td;
    }
    __syncthreads();

    if (tid == 0) {
        double s = 0.0;
#pragma unroll
        for (int w = 0; w < NWARPS; w++) s += sRed[w];
        atomicAdd(&g_sum, s);
        __threadfence();
        unsigned done = atomicAdd(&g_cnt, 1);
        if (done == (unsigned)gridDim.x - 1) {
            double v = *((volatile double*)&g_sum);
            out[0] = (float)(v * inv_n);
            g_sum = 0.0;
            g_cnt = 0;
            __threadfence();
        }
    }
}

// ---------------------------------------------------------------------------

extern "C" void kernel_launch(void* const* d_in, const int* in_sizes, int n_in,
                              void* d_out, int out_size) {
    const float* img1 = (const float*)d_in[0];
    const float* img2 = (const float*)d_in[1];
    float* out = (float*)d_out;

    const int total = in_sizes[0];                  // 16*3*512*512

    const int smem_bytes = (2 * IH * SI_PITCH + 5 * TH * CS_PITCH) * (int)sizeof(ull);
    // 2*26*72*8 + 5*16*71*8 = 29952 + 45440 = 75392

    static bool attr_set = false;
    if (!attr_set) {
        cudaFuncSetAttribute(ssim_main, cudaFuncAttributeMaxDynamicSharedMemorySize,
                             smem_bytes);
        attr_set = true;
    }

    ssim_main<<<NB, NTHREADS, smem_bytes>>>(img1, img2, out, 1.0 / (double)total);
}

// round 13
// speedup vs baseline: 1.0432x; 1.0432x over previous
#include <cuda_runtime.h>

// ---------------------------------------------------------------------------
// SSIM fused kernel: persistent CTAs + 16B cp.async prefetch, sm_100a.
// (16,3,512,512) fp32 pairs -> mean SSIM.
// R13 = R12 resubmit (R12 hit an infra failure; never measured):
//   phase 3 = scalar FFMA-with-immediate streaming conv (no packing movs,
//   weights as instruction immediates); phase 2 packed f32x2.
// ---------------------------------------------------------------------------

#define IMG_H 512
#define IMG_W 512
#define TW 128
#define TH 16
#define IH 26                 // TH + 10
#define SI_PITCH 72           // input smem pitch in float2 units (36 quads)
#define NQUAD 36              // 16B quads per input row
#define NXP 71                // colsum x-pairs per row (pairs 0..70)
#define CS_PITCH 71           // colsum pitch (float2), odd -> conflict-free
#define NTHREADS 288
#define NWARPS 9
#define NB 444                // persistent blocks = 148 SMs x 3 CTAs
#define NTILES (48 * 32 * 4)  // planes x by x bx = 6144

typedef unsigned long long ull;

// ---- compile-time Gaussian weights, double precision (match numpy) --------
constexpr double expser(double x) {
    double t = 1.0, s = 1.0;
    for (int k = 1; k < 100; k++) { t = t * x / (double)k; s += t; }
    return s;
}
constexpr double gk(int i) { double d = (double)(i - 5); return 1.0 / expser(d * d / 4.5); }
constexpr double GSUM = gk(0)+gk(1)+gk(2)+gk(3)+gk(4)+gk(5)+gk(6)+gk(7)+gk(8)+gk(9)+gk(10);
constexpr float WF(int i) { return (float)(gk(i) / GSUM); }
__device__ constexpr float W[11] = {WF(0),WF(1),WF(2),WF(3),WF(4),WF(5),
                                    WF(6),WF(7),WF(8),WF(9),WF(10)};

// ---- f32x2 packed helpers (phase 2 only) ----------------------------------
__device__ __forceinline__ ull fma2(ull a, ull b, ull c) {
    ull d;
    asm("fma.rn.f32x2 %0, %1, %2, %3;" : "=l"(d) : "l"(a), "l"(b), "l"(c));
    return d;
}
__device__ __forceinline__ ull mul2(ull a, ull b) {
    ull d;
    asm("mul.rn.f32x2 %0, %1, %2;" : "=l"(d) : "l"(a), "l"(b));
    return d;
}
__device__ __forceinline__ ull bc2(float w) {
    ull u;
    asm("mov.b64 %0, {%1, %1};" : "=l"(u) : "f"(w));
    return u;
}

__device__ double g_sum;
__device__ unsigned g_cnt;

// ---- 16B cp.async prefetch of one tile's halo'd inputs --------------------
// smem col 0 <-> gx0 = tx0 - 8; quads all-in/all-out -> zfill = zero-pad.
__device__ __forceinline__ void prefetch_tile(int t, int wrp, int lan,
                                              const float* __restrict__ img1,
                                              const float* __restrict__ img2,
                                              ull* sI1, ull* sI2) {
    const int bx = t & 3;
    const int by = (t >> 2) & 31;
    const int plane = t >> 7;
    const int ty0 = by * TH;
    const int gx0 = bx * TW - 8;
    const float* p1 = img1 + (size_t)plane * (IMG_H * IMG_W);
    const float* p2 = img2 + (size_t)plane * (IMG_H * IMG_W);

    for (int y = wrp; y < IH; y += NWARPS) {
        const int gy = ty0 - 5 + y;
        const bool yin = (unsigned)gy < (unsigned)IMG_H;
        const float* r1 = p1 + gy * IMG_W + gx0;
        const float* r2 = p2 + gy * IMG_W + gx0;
        unsigned d1 = (unsigned)__cvta_generic_to_shared(sI1 + y * SI_PITCH);
        unsigned d2 = (unsigned)__cvta_generic_to_shared(sI2 + y * SI_PITCH);
        {
            const int q = lan;                      // quads 0..31
            const int gx = gx0 + 4 * q;
            const int sz = (yin && (unsigned)gx < (unsigned)IMG_W) ? 16 : 0;
            asm volatile("cp.async.cg.shared.global [%0], [%1], 16, %2;"
                         :: "r"(d1 + q * 16), "l"(r1 + 4 * q), "r"(sz));
            asm volatile("cp.async.cg.shared.global [%0], [%1], 16, %2;"
                         :: "r"(d2 + q * 16), "l"(r2 + 4 * q), "r"(sz));
        }
        if (lan < NQUAD - 32) {                     // quads 32..35
            const int q = lan + 32;
            const int gx = gx0 + 4 * q;
            const int sz = (yin && (unsigned)gx < (unsigned)IMG_W) ? 16 : 0;
            asm volatile("cp.async.cg.shared.global [%0], [%1], 16, %2;"
                         :: "r"(d1 + q * 16), "l"(r1 + 4 * q), "r"(sz));
            asm volatile("cp.async.cg.shared.global [%0], [%1], 16, %2;"
                         :: "r"(d2 + q * 16), "l"(r2 + 4 * q), "r"(sz));
        }
    }
}

__global__ __launch_bounds__(NTHREADS, 3)
void ssim_main(const float* __restrict__ img1, const float* __restrict__ img2,
               float* __restrict__ out, double inv_n) {
    extern __shared__ ull smu[];
    ull* sI1 = smu;                               // IH * SI_PITCH
    ull* sI2 = smu + IH * SI_PITCH;
    ull* sCS = smu + 2 * IH * SI_PITCH;           // 5 * TH * CS_PITCH
    __shared__ double sRed[NWARPS];

    const int tid = threadIdx.x;
    const int wrp = tid >> 5;
    const int lan = tid & 31;
    const int bid = blockIdx.x;

    double td = 0.0;

    prefetch_tile(bid, wrp, lan, img1, img2, sI1, sI2);
    asm volatile("cp.async.commit_group;" ::: "memory");

    for (int t = bid; t < NTILES; t += NB) {
        asm volatile("cp.async.wait_group 0;" ::: "memory");
        __syncthreads();                          // sI ready; sCS free

        // ---- phase 2: vertical conv (packed), all 5 quantities ------------
        // 284 tasks = xpair u in [0,71) x strip s in [0,4) of 4 output rows.
        if (tid < NXP * 4) {
            const int u = tid % NXP;
            const int s = tid / NXP;
            const ull* pa = sI1 + (4 * s) * SI_PITCH + u;
            const ull* pb = sI2 + (4 * s) * SI_PITCH + u;
            ull acc[5][4];
#pragma unroll
            for (int q = 0; q < 5; q++)
#pragma unroll
                for (int k = 0; k < 4; k++) acc[q][k] = 0ULL;

#pragma unroll
            for (int j = 0; j < 14; j++) {
                ull a  = pa[j * SI_PITCH];
                ull b  = pb[j * SI_PITCH];
                ull aa = mul2(a, a);
                ull bb = mul2(b, b);
                ull ab = mul2(a, b);
#pragma unroll
                for (int k = 0; k < 4; k++) {
                    if ((unsigned)(j - k) < 11u) {
                        ull wp = bc2(W[j - k]);
                        acc[0][k] = fma2(wp, a,  acc[0][k]);
                        acc[1][k] = fma2(wp, b,  acc[1][k]);
                        acc[2][k] = fma2(wp, aa, acc[2][k]);
                        acc[3][k] = fma2(wp, bb, acc[3][k]);
                        acc[4][k] = fma2(wp, ab, acc[4][k]);
                    }
                }
            }
#pragma unroll
            for (int q = 0; q < 5; q++)
#pragma unroll
                for (int k = 0; k < 4; k++)
                    sCS[(q * TH + 4 * s + k) * CS_PITCH + u] = acc[q][k];
        }
        __syncthreads();                          // sCS ready; sI free

        // ---- prefetch next tile (overlaps phase 3) ------------------------
        {
            int tn = t + NB;
            if (tn < NTILES) prefetch_tile(tn, wrp, lan, img1, img2, sI1, sI2);
            asm volatile("cp.async.commit_group;" ::: "memory");
        }

        // ---- phase 3: horizontal conv, SCALAR FFMA-imm streaming ----------
        // Thread (y, xb) -> out px 8xb+p (p=0..7), smem float origin tx0-8:
        //   px p needs rel floats (8xb)+(p+3)..(p+13); pair i = floats 2i,2i+1;
        //   tap for P.x of pair i is t0 = 2i-3-p, weight W[t0] (immediate).
        if (tid < 256) {
            const int y  = tid & 15;
            const int xb = tid >> 4;

            float m[5][8];
#pragma unroll
            for (int q = 0; q < 5; q++)
#pragma unroll
                for (int p = 0; p < 8; p++) m[q][p] = 0.0f;

#pragma unroll
            for (int q = 0; q < 5; q++) {
                const float2* cs = (const float2*)(sCS + (q * TH + y) * CS_PITCH) + 4 * xb;
#pragma unroll
                for (int i = 1; i <= 10; i++) {
                    float2 P = cs[i];
#pragma unroll
                    for (int p = 0; p < 8; p++) {
                        int t0 = 2 * i - 3 - p;            // tap for P.x
                        if (t0 >= 0 && t0 <= 10)
                            m[q][p] = fmaf(W[t0], P.x, m[q][p]);
                        int t1 = t0 + 1;                   // tap for P.y
                        if (t1 >= 0 && t1 <= 10)
                            m[q][p] = fmaf(W[t1], P.y, m[q][p]);
                    }
                }
            }

            const float C1 = 1e-4f;
            const float C2 = 9e-4f;
            float local = 0.0f;
#pragma unroll
            for (int p = 0; p < 8; p++) {
                float m1 = m[0][p], m2 = m[1][p];
                float m1s = m1 * m1;
                float m2s = m2 * m2;
                float m12 = m1 * m2;
                float s1  = fmaf(-m1, m1, m[2][p]);
                float s2  = fmaf(-m2, m2, m[3][p]);
                float s12 = fmaf(-m1, m2, m[4][p]);
                float num = fmaf(2.0f, m12, C1) * fmaf(2.0f, s12, C2);
                float den = (m1s + m2s + C1) * (s1 + s2 + C2);
                local += __fdividef(num, den);
            }
            td += (double)local;
        }
    }

    // -------- final reduction (once per block) -----------------------------
    {
        unsigned mask = 0xffffffffu;
#pragma unroll
        for (int s = 16; s > 0; s >>= 1) td += __shfl_down_sync(mask, td, s);
        if (lan == 0) sRed[wrp] = td;
    }
    __syncthreads();

    if (tid == 0) {
        double s = 0.0;
#pragma unroll
        for (int w = 0; w < NWARPS; w++) s += sRed[w];
        atomicAdd(&g_sum, s);
        __threadfence();
        unsigned done = atomicAdd(&g_cnt, 1);
        if (done == (unsigned)gridDim.x - 1) {
            double v = *((volatile double*)&g_sum);
            out[0] = (float)(v * inv_n);
            g_sum = 0.0;
            g_cnt = 0;
            __threadfence();
        }
    }
}

// ---------------------------------------------------------------------------

extern "C" void kernel_launch(void* const* d_in, const int* in_sizes, int n_in,
                              void* d_out, int out_size) {
    const float* img1 = (const float*)d_in[0];
    const float* img2 = (const float*)d_in[1];
    float* out = (float*)d_out;

    const int total = in_sizes[0];                  // 16*3*512*512

    const int smem_bytes = (2 * IH * SI_PITCH + 5 * TH * CS_PITCH) * (int)sizeof(ull);
    // 2*26*72*8 + 5*16*71*8 = 29952 + 45440 = 75392

    static bool attr_set = false;
    if (!attr_set) {
        cudaFuncSetAttribute(ssim_main, cudaFuncAttributeMaxDynamicSharedMemorySize,
                             smem_bytes);
        attr_set = true;
    }

    ssim_main<<<NB, NTHREADS, smem_bytes>>>(img1, img2, out, 1.0 / (double)total);
}

// round 14
// speedup vs baseline: 1.0464x; 1.0030x over previous
#include <cuda_runtime.h>

// ---------------------------------------------------------------------------
// SSIM fused kernel: persistent CTAs + 16B cp.async prefetch, sm_100a.
// (16,3,512,512) fp32 pairs -> mean SSIM.
// R14: phase-3 LDS.128 (CS pitch 70, conflict-free), pair-0 colsum dropped
//      (280 dense phase-2 tasks), y-contiguous tile chunks for L2 halo reuse.
// ---------------------------------------------------------------------------

#define IMG_H 512
#define IMG_W 512
#define TW 128
#define TH 16
#define IH 26                 // TH + 10
#define SI_PITCH 72           // input smem pitch in float2 units (36 quads)
#define NQUAD 36              // 16B quads per input row
#define NCS 70                // stored colsum pairs (pairs 1..70)
#define CS_PITCH 70           // colsum pitch (ull), even -> LDS.128-aligned
#define NTHREADS 288
#define NWARPS 9
#define NB 444                // persistent blocks = 148 SMs x 3 CTAs
#define NTILES (48 * 32 * 4)  // 6144: t2 = band*32 + by, band = plane*4 + bx

typedef unsigned long long ull;

// ---- compile-time Gaussian weights, double precision (match numpy) --------
constexpr double expser(double x) {
    double t = 1.0, s = 1.0;
    for (int k = 1; k < 100; k++) { t = t * x / (double)k; s += t; }
    return s;
}
constexpr double gk(int i) { double d = (double)(i - 5); return 1.0 / expser(d * d / 4.5); }
constexpr double GSUM = gk(0)+gk(1)+gk(2)+gk(3)+gk(4)+gk(5)+gk(6)+gk(7)+gk(8)+gk(9)+gk(10);
constexpr float WF(int i) { return (float)(gk(i) / GSUM); }
__device__ constexpr float W[11] = {WF(0),WF(1),WF(2),WF(3),WF(4),WF(5),
                                    WF(6),WF(7),WF(8),WF(9),WF(10)};

// ---- f32x2 packed helpers (phase 2 only) ----------------------------------
__device__ __forceinline__ ull fma2(ull a, ull b, ull c) {
    ull d;
    asm("fma.rn.f32x2 %0, %1, %2, %3;" : "=l"(d) : "l"(a), "l"(b), "l"(c));
    return d;
}
__device__ __forceinline__ ull mul2(ull a, ull b) {
    ull d;
    asm("mul.rn.f32x2 %0, %1, %2;" : "=l"(d) : "l"(a), "l"(b));
    return d;
}
__device__ __forceinline__ ull bc2(float w) {
    ull u;
    asm("mov.b64 %0, {%1, %1};" : "=l"(u) : "f"(w));
    return u;
}

__device__ double g_sum;
__device__ unsigned g_cnt;

// ---- 16B cp.async prefetch of one tile's halo'd inputs --------------------
// smem col 0 <-> gx0 = tx0 - 8; quads all-in/all-out -> zfill = zero-pad.
__device__ __forceinline__ void prefetch_tile(int t2, int wrp, int lan,
                                              const float* __restrict__ img1,
                                              const float* __restrict__ img2,
                                              ull* sI1, ull* sI2) {
    const int by   = t2 & 31;
    const int band = t2 >> 5;
    const int bx   = band & 3;
    const int plane = band >> 2;
    const int ty0 = by * TH;
    const int gx0 = bx * TW - 8;
    const float* p1 = img1 + (size_t)plane * (IMG_H * IMG_W);
    const float* p2 = img2 + (size_t)plane * (IMG_H * IMG_W);

    for (int y = wrp; y < IH; y += NWARPS) {
        const int gy = ty0 - 5 + y;
        const bool yin = (unsigned)gy < (unsigned)IMG_H;
        const float* r1 = p1 + gy * IMG_W + gx0;
        const float* r2 = p2 + gy * IMG_W + gx0;
        unsigned d1 = (unsigned)__cvta_generic_to_shared(sI1 + y * SI_PITCH);
        unsigned d2 = (unsigned)__cvta_generic_to_shared(sI2 + y * SI_PITCH);
        {
            const int q = lan;                      // quads 0..31
            const int gx = gx0 + 4 * q;
            const int sz = (yin && (unsigned)gx < (unsigned)IMG_W) ? 16 : 0;
            asm volatile("cp.async.cg.shared.global [%0], [%1], 16, %2;"
                         :: "r"(d1 + q * 16), "l"(r1 + 4 * q), "r"(sz));
            asm volatile("cp.async.cg.shared.global [%0], [%1], 16, %2;"
                         :: "r"(d2 + q * 16), "l"(r2 + 4 * q), "r"(sz));
        }
        if (lan < NQUAD - 32) {                     // quads 32..35
            const int q = lan + 32;
            const int gx = gx0 + 4 * q;
            const int sz = (yin && (unsigned)gx < (unsigned)IMG_W) ? 16 : 0;
            asm volatile("cp.async.cg.shared.global [%0], [%1], 16, %2;"
                         :: "r"(d1 + q * 16), "l"(r1 + 4 * q), "r"(sz));
            asm volatile("cp.async.cg.shared.global [%0], [%1], 16, %2;"
                         :: "r"(d2 + q * 16), "l"(r2 + 4 * q), "r"(sz));
        }
    }
}

__global__ __launch_bounds__(NTHREADS, 3)
void ssim_main(const float* __restrict__ img1, const float* __restrict__ img2,
               float* __restrict__ out, double inv_n) {
    extern __shared__ ull smu[];
    ull* sI1 = smu;                               // IH * SI_PITCH
    ull* sI2 = smu + IH * SI_PITCH;
    ull* sCS = smu + 2 * IH * SI_PITCH;           // 5 * TH * CS_PITCH
    __shared__ double sRed[NWARPS];

    const int tid = threadIdx.x;
    const int wrp = tid >> 5;
    const int lan = tid & 31;
    const int bid = blockIdx.x;

    // contiguous y-run chunk for this CTA (L2 halo reuse between tiles)
    const int t_beg = (int)(((unsigned)bid * NTILES) / NB);
    const int t_end = (int)(((unsigned)(bid + 1) * NTILES) / NB);

    double td = 0.0;

    if (t_beg < t_end) {
        prefetch_tile(t_beg, wrp, lan, img1, img2, sI1, sI2);
    }
    asm volatile("cp.async.commit_group;" ::: "memory");

    for (int t = t_beg; t < t_end; t++) {
        asm volatile("cp.async.wait_group 0;" ::: "memory");
        __syncthreads();                          // sI ready; sCS free

        // ---- phase 2: vertical conv (packed), all 5 quantities ------------
        // 280 tasks = pair u+1, u in [0,70) x strip s in [0,4) of 4 rows.
        if (tid < NCS * 4) {
            const int u = tid % NCS;
            const int s = tid / NCS;
            const ull* pa = sI1 + (4 * s) * SI_PITCH + (u + 1);
            const ull* pb = sI2 + (4 * s) * SI_PITCH + (u + 1);
            ull acc[5][4];
#pragma unroll
            for (int q = 0; q < 5; q++)
#pragma unroll
                for (int k = 0; k < 4; k++) acc[q][k] = 0ULL;

#pragma unroll
            for (int j = 0; j < 14; j++) {
                ull a  = pa[j * SI_PITCH];
                ull b  = pb[j * SI_PITCH];
                ull aa = mul2(a, a);
                ull bb = mul2(b, b);
                ull ab = mul2(a, b);
#pragma unroll
                for (int k = 0; k < 4; k++) {
                    if ((unsigned)(j - k) < 11u) {
                        ull wp = bc2(W[j - k]);
                        acc[0][k] = fma2(wp, a,  acc[0][k]);
                        acc[1][k] = fma2(wp, b,  acc[1][k]);
                        acc[2][k] = fma2(wp, aa, acc[2][k]);
                        acc[3][k] = fma2(wp, bb, acc[3][k]);
                        acc[4][k] = fma2(wp, ab, acc[4][k]);
                    }
                }
            }
#pragma unroll
            for (int q = 0; q < 5; q++)
#pragma unroll
                for (int k = 0; k < 4; k++)
                    sCS[(q * TH + 4 * s + k) * CS_PITCH + u] = acc[q][k];
        }
        __syncthreads();                          // sCS ready; sI free

        // ---- prefetch next tile (overlaps phase 3) ------------------------
        {
            int tn = t + 1;
            if (tn < t_end) prefetch_tile(tn, wrp, lan, img1, img2, sI1, sI2);
            asm volatile("cp.async.commit_group;" ::: "memory");
        }

        // ---- phase 3: horizontal conv, scalar FFMA-imm, LDS.128 -----------
        // Thread (y, xb): out px 8xb+pp (pp=0..7). sCS idx i holds pair i+1
        // = floats 2i+2, 2i+3 (origin tx0-8). float4 j covers idx 4xb+2j,
        // 4xb+2j+1; component c -> tap t = 4j + c - 1 - pp, valid t in [0,10].
        if (tid < 256) {
            const int y  = tid & 15;
            const int xb = tid >> 4;

            float m[5][8];
#pragma unroll
            for (int q = 0; q < 5; q++)
#pragma unroll
                for (int p = 0; p < 8; p++) m[q][p] = 0.0f;

#pragma unroll
            for (int q = 0; q < 5; q++) {
                const float4* f4 = (const float4*)(sCS + (q * TH + y) * CS_PITCH)
                                   + 2 * xb;
#pragma unroll
                for (int j = 0; j < 5; j++) {
                    float4 P = f4[j];
#pragma unroll
                    for (int p = 0; p < 8; p++) {
                        int t0 = 4 * j - 1 - p;
                        if (t0 >= 0 && t0 <= 10)
                            m[q][p] = fmaf(W[t0], P.x, m[q][p]);
                        if (t0 + 1 >= 0 && t0 + 1 <= 10)
                            m[q][p] = fmaf(W[t0 + 1], P.y, m[q][p]);
                        if (t0 + 2 >= 0 && t0 + 2 <= 10)
                            m[q][p] = fmaf(W[t0 + 2], P.z, m[q][p]);
                        if (t0 + 3 >= 0 && t0 + 3 <= 10)
                            m[q][p] = fmaf(W[t0 + 3], P.w, m[q][p]);
                    }
                }
            }

            const float C1 = 1e-4f;
            const float C2 = 9e-4f;
            float local = 0.0f;
#pragma unroll
            for (int p = 0; p < 8; p++) {
                float m1 = m[0][p], m2 = m[1][p];
                float m1s = m1 * m1;
                float m2s = m2 * m2;
                float m12 = m1 * m2;
                float s1  = fmaf(-m1, m1, m[2][p]);
                float s2  = fmaf(-m2, m2, m[3][p]);
                float s12 = fmaf(-m1, m2, m[4][p]);
                float num = fmaf(2.0f, m12, C1) * fmaf(2.0f, s12, C2);
                float den = (m1s + m2s + C1) * (s1 + s2 + C2);
                local += __fdividef(num, den);
            }
            td += (double)local;
        }
    }

    // -------- final reduction (once per block) -----------------------------
    {
        unsigned mask = 0xffffffffu;
#pragma unroll
        for (int s = 16; s > 0; s >>= 1) td += __shfl_down_sync(mask, td, s);
        if (lan == 0) sRed[wrp] = td;
    }
    __syncthreads();

    if (tid == 0) {
        double s = 0.0;
#pragma unroll
        for (int w = 0; w < NWARPS; w++) s += sRed[w];
        atomicAdd(&g_sum, s);
        __threadfence();
        unsigned done = atomicAdd(&g_cnt, 1);
        if (done == (unsigned)gridDim.x - 1) {
            double v = *((volatile double*)&g_sum);
            out[0] = (float)(v * inv_n);
            g_sum = 0.0;
            g_cnt = 0;
            __threadfence();
        }
    }
}

// ---------------------------------------------------------------------------

extern "C" void kernel_launch(void* const* d_in, const int* in_sizes, int n_in,
                              void* d_out, int out_size) {
    const float* img1 = (const float*)d_in[0];
    const float* img2 = (const float*)d_in[1];
    float* out = (float*)d_out;

    const int total = in_sizes[0];                  // 16*3*512*512

    const int smem_bytes = (2 * IH * SI_PITCH + 5 * TH * CS_PITCH) * (int)sizeof(ull);
    // 2*26*72*8 + 5*16*70*8 = 29952 + 44800 = 74752

    static bool attr_set = false;
    if (!attr_set) {
        cudaFuncSetAttribute(ssim_main, cudaFuncAttributeMaxDynamicSharedMemorySize,
                             smem_bytes);
        attr_set = true;
    }

    ssim_main<<<NB, NTHREADS, smem_bytes>>>(img1, img2, out, 1.0 / (double)total);
}

// round 17
// speedup vs baseline: 1.1928x; 1.1400x over previous
#include <cuda_runtime.h>

// ---------------------------------------------------------------------------
// SSIM fused kernel: persistent CTAs + 16B cp.async prefetch, sm_100a.
// (16,3,512,512) fp32 pairs -> mean SSIM.
// R17: 4-quantity reformulation (x, y, (x+y)^2, (x-y)^2) -- SSIM only needs
//      sigma1^2+sigma2^2 and sigma12, both recoverable from s^2/d^2 convs.
//      All fp32 (R16 showed 16-bit colsums break the sigma cancellation).
//      Structure otherwise identical to R14 (95.9 us, validated).
// ---------------------------------------------------------------------------

#define IMG_H 512
#define IMG_W 512
#define TW 128
#define TH 16
#define IH 26                 // TH + 10
#define SI_PITCH 72           // input smem pitch in float2 units (36 quads)
#define NQUAD 36              // 16B quads per input row
#define NCS 70                // stored colsum pairs (pairs 1..70)
#define CS_PITCH 70           // colsum pitch (ull), even -> LDS.128-aligned
#define NQTY 4                // x, y, s^2, d^2
#define NTHREADS 288
#define NWARPS 9
#define NB 444                // persistent blocks = 148 SMs x 3 CTAs
#define NTILES (48 * 32 * 4)  // t2 = band*32 + by, band = plane*4 + bx

typedef unsigned long long ull;

// ---- compile-time Gaussian weights, double precision (match numpy) --------
constexpr double expser(double x) {
    double t = 1.0, s = 1.0;
    for (int k = 1; k < 100; k++) { t = t * x / (double)k; s += t; }
    return s;
}
constexpr double gk(int i) { double d = (double)(i - 5); return 1.0 / expser(d * d / 4.5); }
constexpr double GSUM = gk(0)+gk(1)+gk(2)+gk(3)+gk(4)+gk(5)+gk(6)+gk(7)+gk(8)+gk(9)+gk(10);
constexpr float WF(int i) { return (float)(gk(i) / GSUM); }
__device__ constexpr float W[11] = {WF(0),WF(1),WF(2),WF(3),WF(4),WF(5),
                                    WF(6),WF(7),WF(8),WF(9),WF(10)};

// ---- f32x2 packed helpers (phase 2) ---------------------------------------
__device__ __forceinline__ ull fma2(ull a, ull b, ull c) {
    ull d;
    asm("fma.rn.f32x2 %0, %1, %2, %3;" : "=l"(d) : "l"(a), "l"(b), "l"(c));
    return d;
}
__device__ __forceinline__ ull mul2(ull a, ull b) {
    ull d;
    asm("mul.rn.f32x2 %0, %1, %2;" : "=l"(d) : "l"(a), "l"(b));
    return d;
}
__device__ __forceinline__ ull add2(ull a, ull b) {
    ull d;
    asm("add.rn.f32x2 %0, %1, %2;" : "=l"(d) : "l"(a), "l"(b));
    return d;
}
__device__ __forceinline__ ull bc2(float w) {
    ull u;
    asm("mov.b64 %0, {%1, %1};" : "=l"(u) : "f"(w));
    return u;
}

__device__ double g_sum;
__device__ unsigned g_cnt;

// ---- 16B cp.async prefetch of one tile's halo'd inputs --------------------
__device__ __forceinline__ void prefetch_tile(int t2, int wrp, int lan,
                                              const float* __restrict__ img1,
                                              const float* __restrict__ img2,
                                              ull* sI1, ull* sI2) {
    const int by   = t2 & 31;
    const int band = t2 >> 5;
    const int bx   = band & 3;
    const int plane = band >> 2;
    const int ty0 = by * TH;
    const int gx0 = bx * TW - 8;
    const float* p1 = img1 + (size_t)plane * (IMG_H * IMG_W);
    const float* p2 = img2 + (size_t)plane * (IMG_H * IMG_W);

    for (int y = wrp; y < IH; y += NWARPS) {
        const int gy = ty0 - 5 + y;
        const bool yin = (unsigned)gy < (unsigned)IMG_H;
        const float* r1 = p1 + gy * IMG_W + gx0;
        const float* r2 = p2 + gy * IMG_W + gx0;
        unsigned d1 = (unsigned)__cvta_generic_to_shared(sI1 + y * SI_PITCH);
        unsigned d2 = (unsigned)__cvta_generic_to_shared(sI2 + y * SI_PITCH);
        {
            const int q = lan;                      // quads 0..31
            const int gx = gx0 + 4 * q;
            const int sz = (yin && (unsigned)gx < (unsigned)IMG_W) ? 16 : 0;
            asm volatile("cp.async.cg.shared.global [%0], [%1], 16, %2;"
                         :: "r"(d1 + q * 16), "l"(r1 + 4 * q), "r"(sz));
            asm volatile("cp.async.cg.shared.global [%0], [%1], 16, %2;"
                         :: "r"(d2 + q * 16), "l"(r2 + 4 * q), "r"(sz));
        }
        if (lan < NQUAD - 32) {                     // quads 32..35
            const int q = lan + 32;
            const int gx = gx0 + 4 * q;
            const int sz = (yin && (unsigned)gx < (unsigned)IMG_W) ? 16 : 0;
            asm volatile("cp.async.cg.shared.global [%0], [%1], 16, %2;"
                         :: "r"(d1 + q * 16), "l"(r1 + 4 * q), "r"(sz));
            asm volatile("cp.async.cg.shared.global [%0], [%1], 16, %2;"
                         :: "r"(d2 + q * 16), "l"(r2 + 4 * q), "r"(sz));
        }
    }
}

__global__ __launch_bounds__(NTHREADS, 3)
void ssim_main(const float* __restrict__ img1, const float* __restrict__ img2,
               float* __restrict__ out, double inv_n) {
    extern __shared__ ull smu[];
    ull* sI1 = smu;                               // IH * SI_PITCH
    ull* sI2 = smu + IH * SI_PITCH;
    ull* sCS = smu + 2 * IH * SI_PITCH;           // NQTY * TH * CS_PITCH
    __shared__ double sRed[NWARPS];

    const int tid = threadIdx.x;
    const int wrp = tid >> 5;
    const int lan = tid & 31;
    const int bid = blockIdx.x;

    const int t_beg = (int)(((unsigned)bid * NTILES) / NB);
    const int t_end = (int)(((unsigned)(bid + 1) * NTILES) / NB);

    double td = 0.0;

    if (t_beg < t_end) {
        prefetch_tile(t_beg, wrp, lan, img1, img2, sI1, sI2);
    }
    asm volatile("cp.async.commit_group;" ::: "memory");

    for (int t = t_beg; t < t_end; t++) {
        asm volatile("cp.async.wait_group 0;" ::: "memory");
        __syncthreads();                          // sI ready; sCS free

        // ---- phase 2: vertical conv (packed), 4 quantities ----------------
        // 280 tasks = pair u+1, u in [0,70) x strip s in [0,4) of 4 rows.
        if (tid < NCS * 4) {
            const int u = tid % NCS;
            const int s = tid / NCS;
            const ull* pa = sI1 + (4 * s) * SI_PITCH + (u + 1);
            const ull* pb = sI2 + (4 * s) * SI_PITCH + (u + 1);
            const ull NEG1 = bc2(-1.0f);
            ull acc[NQTY][4];
#pragma unroll
            for (int q = 0; q < NQTY; q++)
#pragma unroll
                for (int k = 0; k < 4; k++) acc[q][k] = 0ULL;

#pragma unroll
            for (int j = 0; j < 14; j++) {
                ull a  = pa[j * SI_PITCH];
                ull b  = pb[j * SI_PITCH];
                ull sv = add2(a, b);
                ull dv = fma2(NEG1, b, a);        // a - b
                ull ss = mul2(sv, sv);
                ull dd = mul2(dv, dv);
#pragma unroll
                for (int k = 0; k < 4; k++) {
                    if ((unsigned)(j - k) < 11u) {
                        ull wp = bc2(W[j - k]);
                        acc[0][k] = fma2(wp, a,  acc[0][k]);
                        acc[1][k] = fma2(wp, b,  acc[1][k]);
                        acc[2][k] = fma2(wp, ss, acc[2][k]);
                        acc[3][k] = fma2(wp, dd, acc[3][k]);
                    }
                }
            }
#pragma unroll
            for (int q = 0; q < NQTY; q++)
#pragma unroll
                for (int k = 0; k < 4; k++)
                    sCS[(q * TH + 4 * s + k) * CS_PITCH + u] = acc[q][k];
        }
        __syncthreads();                          // sCS ready; sI free

        // ---- prefetch next tile (overlaps phase 3) ------------------------
        {
            int tn = t + 1;
            if (tn < t_end) prefetch_tile(tn, wrp, lan, img1, img2, sI1, sI2);
            asm volatile("cp.async.commit_group;" ::: "memory");
        }

        // ---- phase 3: horizontal conv, scalar FFMA-imm, LDS.128 -----------
        // (identical mapping to R14) Thread (y, xb): out px 8xb+pp. sCS idx i
        // holds pair i+1 (floats 2i+2,2i+3 rel tx0-8). float4 j: component c
        // -> tap tt = 4j + c - 1 - pp, valid tt in [0,10].
        if (tid < 256) {
            const int y  = tid & 15;
            const int xb = tid >> 4;

            float m[NQTY][8];
#pragma unroll
            for (int q = 0; q < NQTY; q++)
#pragma unroll
                for (int p = 0; p < 8; p++) m[q][p] = 0.0f;

#pragma unroll
            for (int q = 0; q < NQTY; q++) {
                const float4* f4 = (const float4*)(sCS + (q * TH + y) * CS_PITCH)
                                   + 2 * xb;
#pragma unroll
                for (int j = 0; j < 5; j++) {
                    float4 P = f4[j];
#pragma unroll
                    for (int p = 0; p < 8; p++) {
                        int t0 = 4 * j - 1 - p;
                        if (t0 >= 0 && t0 <= 10)
                            m[q][p] = fmaf(W[t0], P.x, m[q][p]);
                        if (t0 + 1 >= 0 && t0 + 1 <= 10)
                            m[q][p] = fmaf(W[t0 + 1], P.y, m[q][p]);
                        if (t0 + 2 >= 0 && t0 + 2 <= 10)
                            m[q][p] = fmaf(W[t0 + 2], P.z, m[q][p]);
                        if (t0 + 3 >= 0 && t0 + 3 <= 10)
                            m[q][p] = fmaf(W[t0 + 3], P.w, m[q][p]);
                    }
                }
            }

            const float C1 = 1e-4f;
            const float C2 = 9e-4f;
            float local = 0.0f;
#pragma unroll
            for (int p = 0; p < 8; p++) {
                float m1 = m[0][p], m2 = m[1][p];
                float ms = m[2][p], md = m[3][p];
                float m12 = m1 * m2;
                float musq = fmaf(m1, m1, m2 * m2);           // mu1^2 + mu2^2
                float tdf = ms - md;
                float s12 = fmaf(0.25f, tdf, -m12);           // sigma12
                float u   = ms + md;
                float ssum = fmaf(-m1, m1, fmaf(-m2, m2, 0.5f * u)); // s1+s2
                float num = fmaf(2.0f, m12, C1) * fmaf(2.0f, s12, C2);
                float den = (musq + C1) * (ssum + C2);
                local += __fdividef(num, den);
            }
            td += (double)local;
        }
    }

    // -------- final reduction (once per block) -----------------------------
    {
        unsigned mask = 0xffffffffu;
#pragma unroll
        for (int s = 16; s > 0; s >>= 1) td += __shfl_down_sync(mask, td, s);
        if (lan == 0) sRed[wrp] = td;
    }
    __syncthreads();

    if (tid == 0) {
        double s = 0.0;
#pragma unroll
        for (int w = 0; w < NWARPS; w++) s += sRed[w];
        atomicAdd(&g_sum, s);
        __threadfence();
        unsigned done = atomicAdd(&g_cnt, 1);
        if (done == (unsigned)gridDim.x - 1) {
            double v = *((volatile double*)&g_sum);
            out[0] = (float)(v * inv_n);
            g_sum = 0.0;
            g_cnt = 0;
            __threadfence();
        }
    }
}

// ---------------------------------------------------------------------------

extern "C" void kernel_launch(void* const* d_in, const int* in_sizes, int n_in,
                              void* d_out, int out_size) {
    const float* img1 = (const float*)d_in[0];
    const float* img2 = (const float*)d_in[1];
    float* out = (float*)d_out;

    const int total = in_sizes[0];                  // 16*3*512*512

    const int smem_bytes = (2 * IH * SI_PITCH + NQTY * TH * CS_PITCH) * (int)sizeof(ull);
    // 2*26*72*8 + 4*16*70*8 = 29952 + 35840 = 65792

    static bool attr_set = false;
    if (!attr_set) {
        cudaFuncSetAttribute(ssim_main, cudaFuncAttributeMaxDynamicSharedMemorySize,
                             smem_bytes);
        attr_set = true;
    }

    ssim_main<<<NB, NTHREADS, smem_bytes>>>(img1, img2, out, 1.0 / (double)total);
}